// round 3
// baseline (speedup 1.0000x reference)
#include <cuda_runtime.h>

typedef unsigned long long u64;

#define PHYS_DT (1.0f/60.0f)
#define NU_C    0.001f

__device__ __forceinline__ float softplusf(float x){
    return fmaxf(x, 0.0f) + log1pf(expf(-fabsf(x)));
}
__device__ __forceinline__ u64 pack2(float a, float b){
    u64 r; asm("mov.b64 %0, {%1,%2};" : "=l"(r) : "f"(a), "f"(b)); return r;
}
__device__ __forceinline__ float2 unpk(u64 a){
    float2 v; asm("mov.b64 {%0,%1}, %2;" : "=f"(v.x), "=f"(v.y) : "l"(a)); return v;
}
__device__ __forceinline__ u64 f2fma(u64 a, u64 b, u64 c){
    u64 d; asm("fma.rn.f32x2 %0,%1,%2,%3;" : "=l"(d) : "l"(a), "l"(b), "l"(c)); return d;
}
__device__ __forceinline__ u64 f2add(u64 a, u64 b){
    u64 d; asm("add.rn.f32x2 %0,%1,%2;" : "=l"(d) : "l"(a), "l"(b)); return d;
}
__device__ __forceinline__ u64 f2mul(u64 a, u64 b){
    u64 d; asm("mul.rn.f32x2 %0,%1,%2;" : "=l"(d) : "l"(a), "l"(b)); return d;
}

extern __shared__ __align__(16) char dynsmem[];

// grid: 296 blocks x 512 threads.
// blocks [0,256): fluid, one batch PAIR per block, f32x2-packed conv.
// blocks [256,296): particle, 8 batches in parallel, up to 2 rounds.
__global__ void __launch_bounds__(512, 1) fused_kernel(
    const float* __restrict__ pos, const float* __restrict__ vel,
    const float* __restrict__ rot, const float* __restrict__ omg,
    const float* __restrict__ mass, const float* __restrict__ inertia,
    const float* __restrict__ contacts, const float* __restrict__ energy,
    const float* __restrict__ fluid, const float* __restrict__ Fext,
    const float* __restrict__ tau, const float* __restrict__ logA,
    const float* __restrict__ logk, const float* __restrict__ logb,
    const float* __restrict__ conv_w, float* __restrict__ out)
{
    if (blockIdx.x < 256) {
        // ================= FLUID (batch pair, f32x2) =================
        u64* S = (u64*)dynsmem;          // 2 buffers x 13056 u64
        __shared__ u64 Wp[81];
        __shared__ u64 redsh[48];
        __shared__ u64 meansh[3];

        const int tid = threadIdx.x;
        const int hs = tid >> 8;              // h half: 0 -> h 0..7, 1 -> h 8..15
        const int d  = (tid >> 4) & 15;
        const int w  = tid & 15;
        const int h0 = hs << 3;
        const int lane = tid & 31;
        const int RS = 16, SS = 272, CS = 4352, BUF = 13056;

        const int b0 = blockIdx.x * 2;
        const float* f0 = fluid + (size_t)b0 * 12288;
        const float* f1 = f0 + 12288;

        if (tid < 81) { float x = conv_w[tid]; Wp[tid] = pack2(x, x); }

        for (int idx = tid; idx < 12288; idx += 512) {
            float a = f0[idx], bv = f1[idx];
            int cell = idx / 3, c = idx - cell*3;
            int dd = cell >> 8, hh = (cell >> 4) & 15, ww = cell & 15;
            S[c*CS + dd*SS + hh*RS + ww] = pack2(a, bv);
        }
        __syncthreads();

        u64 acc[24];
        #pragma unroll
        for (int q = 0; q < 24; q++) acc[q] = 0ull;

        const bool dmv = (d > 0), dpv = (d < 15);
        const u64 nu2 = pack2(NU_C, NU_C);

        #pragma unroll 1
        for (int s = 0; s < 4; s++) {
            const u64* cur = S + (s & 1)*BUF;
            u64*       nxt = S + ((s + 1) & 1)*BUF;
            const float awf = (s == 0 || s == 3) ? 1.f : 2.f;
            const float cof = (s == 2) ? PHYS_DT : 0.5f*PHYS_DT;
            const u64 aw2 = pack2(awf, awf);
            const u64 co2 = pack2(cof, cof);
            const bool wr = (s < 3);
            u64 ps0 = 0, ps1 = 0, ps2 = 0;

            #pragma unroll
            for (int c = 0; c < 3; c++) {
                u64 W[27];
                #pragma unroll
                for (int t = 0; t < 27; t++) W[t] = Wp[c*27 + t];
                const u64* bp  = cur + c*CS + d*SS + w;
                const u64* bpm = bp - SS;
                const u64* bpp = bp + SS;
                const int hm1 = hs ? 7 : 0;

                u64 r00 = (hs && dmv) ? bpm[hm1*RS] : 0ull;
                u64 r10 =  hs         ? bp [hm1*RS] : 0ull;
                u64 r20 = (hs && dpv) ? bpp[hm1*RS] : 0ull;
                u64 r01 = dmv ? bpm[h0*RS] : 0ull;
                u64 r11 =       bp [h0*RS];
                u64 r21 = dpv ? bpp[h0*RS] : 0ull;
                u64 r02 = dmv ? bpm[(h0+1)*RS] : 0ull;
                u64 r12 =       bp [(h0+1)*RS];
                u64 r22 = dpv ? bpp[(h0+1)*RS] : 0ull;
                u64 psc = 0;

                #pragma unroll
                for (int hh = 0; hh < 8; hh++) {
                    const int h = h0 + hh;
                    u64 bb0 = f2mul(W[0], r00);
                    bb0 = f2fma(W[ 3], r01, bb0); bb0 = f2fma(W[ 6], r02, bb0);
                    bb0 = f2fma(W[ 9], r10, bb0); bb0 = f2fma(W[12], r11, bb0);
                    bb0 = f2fma(W[15], r12, bb0); bb0 = f2fma(W[18], r20, bb0);
                    bb0 = f2fma(W[21], r21, bb0); bb0 = f2fma(W[24], r22, bb0);
                    u64 bb1 = f2mul(W[1], r00);
                    bb1 = f2fma(W[ 4], r01, bb1); bb1 = f2fma(W[ 7], r02, bb1);
                    bb1 = f2fma(W[10], r10, bb1); bb1 = f2fma(W[13], r11, bb1);
                    bb1 = f2fma(W[16], r12, bb1); bb1 = f2fma(W[19], r20, bb1);
                    bb1 = f2fma(W[22], r21, bb1); bb1 = f2fma(W[25], r22, bb1);
                    u64 bb2 = f2mul(W[2], r00);
                    bb2 = f2fma(W[ 5], r01, bb2); bb2 = f2fma(W[ 8], r02, bb2);
                    bb2 = f2fma(W[11], r10, bb2); bb2 = f2fma(W[14], r11, bb2);
                    bb2 = f2fma(W[17], r12, bb2); bb2 = f2fma(W[20], r20, bb2);
                    bb2 = f2fma(W[23], r21, bb2); bb2 = f2fma(W[26], r22, bb2);

                    u64 lft = __shfl_up_sync(0xffffffffu, bb0, 1);
                    if (w == 0)  lft = 0ull;
                    u64 rgt = __shfl_down_sync(0xffffffffu, bb2, 1);
                    if (w == 15) rgt = 0ull;
                    u64 kv = f2mul(nu2, f2add(f2add(lft, bb1), rgt));
                    acc[c*8 + hh] = f2fma(aw2, kv, acc[c*8 + hh]);
                    if (wr) {
                        int gidx = ((d << 8) + (h << 4) + w)*3 + c;
                        u64 u0v = pack2(f0[gidx], f1[gidx]);
                        u64 sr = f2fma(co2, kv, u0v);
                        nxt[c*CS + d*SS + h*RS + w] = sr;
                        psc = f2add(psc, sr);
                    }
                    r00 = r01; r01 = r02;
                    r10 = r11; r11 = r12;
                    r20 = r21; r21 = r22;
                    const int hn = h + 2;
                    const bool hv = (hn < 16);
                    const int hns = hv ? hn : 0;
                    r02 = (hv && dmv) ? bpm[hns*RS] : 0ull;
                    r12 =  hv         ? bp [hns*RS] : 0ull;
                    r22 = (hv && dpv) ? bpp[hns*RS] : 0ull;
                }
                if (c == 0) ps0 = psc; else if (c == 1) ps1 = psc; else ps2 = psc;
            }

            if (wr) {
                #pragma unroll
                for (int off = 16; off; off >>= 1) {
                    ps0 = f2add(ps0, __shfl_xor_sync(0xffffffffu, ps0, off));
                    ps1 = f2add(ps1, __shfl_xor_sync(0xffffffffu, ps1, off));
                    ps2 = f2add(ps2, __shfl_xor_sync(0xffffffffu, ps2, off));
                }
                int wi = tid >> 5;
                if (lane == 0) {
                    redsh[wi*3+0] = ps0; redsh[wi*3+1] = ps1; redsh[wi*3+2] = ps2;
                }
                __syncthreads();
                if (tid < 3) {
                    u64 sm = 0;
                    #pragma unroll
                    for (int q = 0; q < 16; q++) sm = f2add(sm, redsh[q*3 + tid]);
                    meansh[tid] = f2mul(sm, pack2(-1.0f/4096.0f, -1.0f/4096.0f));
                }
                __syncthreads();
                #pragma unroll
                for (int c = 0; c < 3; c++) {
                    u64 mn = meansh[c];
                    #pragma unroll
                    for (int hh = 0; hh < 8; hh++) {
                        int off = c*CS + d*SS + (h0+hh)*RS + w;
                        nxt[off] = f2add(nxt[off], mn);
                    }
                }
                __syncthreads();
            }
        }

        // final: rv = u0 + dt/6 * acc  ->  demean  ->  store both batches
        {
            const u64 dt6 = pack2(PHYS_DT/6.0f, PHYS_DT/6.0f);
            u64 pf0 = 0, pf1 = 0, pf2 = 0;
            #pragma unroll
            for (int c = 0; c < 3; c++) {
                u64 psc = 0;
                #pragma unroll
                for (int hh = 0; hh < 8; hh++) {
                    int h = h0 + hh;
                    int gidx = ((d << 8) + (h << 4) + w)*3 + c;
                    u64 u0v = pack2(f0[gidx], f1[gidx]);
                    u64 rv = f2fma(dt6, acc[c*8 + hh], u0v);
                    S[c*CS + d*SS + h*RS + w] = rv;   // buf0: free (stage 3 read buf1)
                    psc = f2add(psc, rv);
                }
                if (c == 0) pf0 = psc; else if (c == 1) pf1 = psc; else pf2 = psc;
            }
            #pragma unroll
            for (int off = 16; off; off >>= 1) {
                pf0 = f2add(pf0, __shfl_xor_sync(0xffffffffu, pf0, off));
                pf1 = f2add(pf1, __shfl_xor_sync(0xffffffffu, pf1, off));
                pf2 = f2add(pf2, __shfl_xor_sync(0xffffffffu, pf2, off));
            }
            int wi = tid >> 5;
            if (lane == 0) {
                redsh[wi*3+0] = pf0; redsh[wi*3+1] = pf1; redsh[wi*3+2] = pf2;
            }
            __syncthreads();
            if (tid < 3) {
                u64 sm = 0;
                #pragma unroll
                for (int q = 0; q < 16; q++) sm = f2add(sm, redsh[q*3 + tid]);
                meansh[tid] = f2mul(sm, pack2(-1.0f/4096.0f, -1.0f/4096.0f));
            }
            __syncthreads();

            float* o0 = out + (size_t)b0*13313 + 1025;
            float* o1 = o0 + 13313;
            for (int idx = tid; idx < 12288; idx += 512) {
                int cell = idx / 3, c = idx - cell*3;
                int dd = cell >> 8, hh = (cell >> 4) & 15, ww = cell & 15;
                u64 v = f2add(S[c*CS + dd*SS + hh*RS + ww], meansh[c]);
                float2 fv = unpk(v);
                o0[idx] = fv.x;
                o1[idx] = fv.y;
            }
        }
    } else {
        // ================= PARTICLES (8 batches / block, <=2 rounds) =========
        float* P = (float*)dynsmem;
        const int sub = threadIdx.x >> 6;
        const int i   = threadIdx.x & 63;
        float*  ct   = P + sub*4680;                 // [64*65]
        float4* sp   = (float4*)(ct + 4160);         // [64]
        float4* sv   = sp + 64;                      // [64]
        float*  redw = ct + 4672;                    // [2]

        #pragma unroll 1
        for (int rnd = 0; rnd < 2; rnd++) {
            const int pb = (blockIdx.x - 256)*8 + sub + rnd*320;
            const bool act = (pb < 512);
            const int b = act ? pb : 0;
            __syncthreads();   // shared reuse safe across rounds

            const int gi = b*64 + i;
            const float px=pos[gi*3+0], py=pos[gi*3+1], pz=pos[gi*3+2];
            const float vx=vel[gi*3+0], vy=vel[gi*3+1], vz=vel[gi*3+2];
            const float rw=rot[gi*4+0], rx=rot[gi*4+1], ry=rot[gi*4+2], rz=rot[gi*4+3];
            const float ox=omg[gi*3+0], oy=omg[gi*3+1], oz=omg[gi*3+2];
            const float Ix=inertia[gi*3+0], Iy=inertia[gi*3+1], Iz=inertia[gi*3+2];
            const float fx=Fext[gi*3+0], fy=Fext[gi*3+1], fz=Fext[gi*3+2];
            const float tx=tau[gi*3+0], ty=tau[gi*3+1], tz=tau[gi*3+2];
            const float m    = mass[gi];
            const float kk   = softplusf(logk[0]);
            const float bb   = softplusf(logb[0]);
            const float dragc= -0.5f*1.225f*0.47f*softplusf(logA[i]);
            const float minv = 1.0f/m;
            const float Iix=1.0f/fmaxf(Ix,1e-6f), Iiy=1.0f/fmaxf(Iy,1e-6f), Iiz=1.0f/fmaxf(Iz,1e-6f);

            #pragma unroll 8
            for (int r = 0; r < 64; r++)
                ct[i*65 + r] = contacts[b*4096 + r*64 + i];
            sp[i] = make_float4(px,py,pz,0.f);
            sv[i] = make_float4(vx,vy,vz,0.f);
            __syncthreads();

            float cpx=px,cpy=py,cpz=pz, cvx=vx,cvy=vy,cvz=vz;
            float qw=rw,qx=rx,qy=ry,qz=rz, cox=ox,coy=oy,coz=oz;
            float aPx=0,aPy=0,aPz=0, aVx=0,aVy=0,aVz=0;
            float aRw=0,aRx=0,aRy=0,aRz=0, aWx=0,aWy=0,aWz=0, aE=0;
            float dvx,dvy,dvz, drw,drx,dry,drz, dwx,dwy,dwz, dE;

            auto deriv = [&]() {
                float vm = fmaxf(sqrtf(cvx*cvx + cvy*cvy + cvz*cvz), 1e-6f);
                float dc = dragc * vm;
                float fdx = dc*cvx, fdy = dc*cvy, fdz = dc*cvz;
                float fcx = 0.f, fcy = 0.f, fcz = 0.f;
                #pragma unroll 8
                for (int j = 0; j < 64; j++) {
                    float4 pj = sp[j];
                    float4 vj = sv[j];
                    float dx = pj.x - cpx, dy = pj.y - cpy, dz = pj.z - cpz;
                    float d2 = fmaf(dx,dx, fmaf(dy,dy, dz*dz));
                    float ri = rsqrtf(fmaxf(d2, 1e-12f));
                    float pen = fmaxf(1.0f - d2*ri, 0.0f);
                    float kp = kk * pen * ri;
                    float cf = bb * ct[j*65 + i];
                    fcx += kp*dx + cf*(vj.x - cvx);
                    fcy += kp*dy + cf*(vj.y - cvy);
                    fcz += kp*dz + cf*(vj.z - cvz);
                }
                dvx = (fx + fdx + fcx) * minv;
                dvy = (fy + fdy + fcy) * minv;
                dvz = (fz + fdz + fcz) * minv - 9.81f;
                float Iox = Ix*cox, Ioy = Iy*coy, Ioz = Iz*coz;
                dwx = (tx - (coy*Ioz - coz*Ioy)) * Iix;
                dwy = (ty - (coz*Iox - cox*Ioz)) * Iiy;
                dwz = (tz - (cox*Ioy - coy*Iox)) * Iiz;
                drw = 0.5f*(-qx*cox - qy*coy - qz*coz);
                drx = 0.5f*( qw*cox + qy*coz - qz*coy);
                dry = 0.5f*( qw*coy - qx*coz + qz*cox);
                drz = 0.5f*( qw*coz + qx*coy - qy*cox);
                dE  = (fx + fdx)*cvx + (fy + fdy)*cvy + (fz + fdz)*cvz;
            };
            auto accum = [&](float wgt) {
                aPx += wgt*cvx; aPy += wgt*cvy; aPz += wgt*cvz;
                aVx += wgt*dvx; aVy += wgt*dvy; aVz += wgt*dvz;
                aRw += wgt*drw; aRx += wgt*drx; aRy += wgt*dry; aRz += wgt*drz;
                aWx += wgt*dwx; aWy += wgt*dwy; aWz += wgt*dwz;
                aE  += wgt*dE;
            };
            auto advance = [&](float h) {
                float npx = px + h*cvx, npy = py + h*cvy, npz = pz + h*cvz;
                cvx = vx + h*dvx; cvy = vy + h*dvy; cvz = vz + h*dvz;
                cpx = npx; cpy = npy; cpz = npz;
                float nqw = rw + h*drw, nqx = rx + h*drx, nqy = ry + h*dry, nqz = rz + h*drz;
                float nn  = fmaxf(sqrtf(nqw*nqw + nqx*nqx + nqy*nqy + nqz*nqz), 1e-12f);
                float inn = 1.0f/nn;
                qw = nqw*inn; qx = nqx*inn; qy = nqy*inn; qz = nqz*inn;
                cox = ox + h*dwx; coy = oy + h*dwy; coz = oz + h*dwz;
                __syncthreads();
                sp[i] = make_float4(cpx,cpy,cpz,0.f);
                sv[i] = make_float4(cvx,cvy,cvz,0.f);
                __syncthreads();
            };

            const int base = b * 13313;

            deriv(); accum(1.f);
            if (act) {
                int fb = base + 832 + i*3;
                out[fb+0] = fx + m*dvx;
                out[fb+1] = fy + m*dvy;
                out[fb+2] = fz + m*dvz;
            }
            advance(0.5f*PHYS_DT);
            deriv(); accum(2.f);
            advance(0.5f*PHYS_DT);
            deriv(); accum(2.f);
            advance(PHYS_DT);
            deriv(); accum(1.f);

            const float s6 = PHYS_DT/6.0f;
            if (act) {
                out[base + i*3+0] = px + s6*aPx;
                out[base + i*3+1] = py + s6*aPy;
                out[base + i*3+2] = pz + s6*aPz;
                out[base + 192 + i*3+0] = vx + s6*aVx;
                out[base + 192 + i*3+1] = vy + s6*aVy;
                out[base + 192 + i*3+2] = vz + s6*aVz;
                float nqw = rw + s6*aRw, nqx = rx + s6*aRx, nqy = ry + s6*aRy, nqz = rz + s6*aRz;
                float nn  = fmaxf(sqrtf(nqw*nqw + nqx*nqx + nqy*nqy + nqz*nqz), 1e-12f);
                float inn = 1.0f/nn;
                out[base + 384 + i*4+0] = nqw*inn;
                out[base + 384 + i*4+1] = nqx*inn;
                out[base + 384 + i*4+2] = nqy*inn;
                out[base + 384 + i*4+3] = nqz*inn;
                out[base + 640 + i*3+0] = ox + s6*aWx;
                out[base + 640 + i*3+1] = oy + s6*aWy;
                out[base + 640 + i*3+2] = oz + s6*aWz;
            }
            float e = aE;
            #pragma unroll
            for (int off = 16; off; off >>= 1)
                e += __shfl_down_sync(0xffffffffu, e, off);
            if ((i & 31) == 0) redw[i >> 5] = e;
            __syncthreads();
            if (act && i == 0) out[base + 1024] = energy[b] + s6*(redw[0] + redw[1]);
        }
    }
}

// ---------------------------------------------------------------------------
extern "C" void kernel_launch(void* const* d_in, const int* in_sizes, int n_in,
                              void* d_out, int out_size)
{
    (void)in_sizes; (void)n_in; (void)out_size;
    const float* pos      = (const float*)d_in[0];
    const float* vel      = (const float*)d_in[1];
    const float* rot      = (const float*)d_in[2];
    const float* omg      = (const float*)d_in[3];
    const float* mass     = (const float*)d_in[4];
    const float* inertia  = (const float*)d_in[5];
    const float* contacts = (const float*)d_in[6];
    const float* energy   = (const float*)d_in[7];
    const float* fluid    = (const float*)d_in[8];
    const float* Fext     = (const float*)d_in[9];
    const float* tau      = (const float*)d_in[10];
    const float* logA     = (const float*)d_in[11];
    const float* logk     = (const float*)d_in[12];
    const float* logb     = (const float*)d_in[13];
    const float* conv_w   = (const float*)d_in[14];
    float* out = (float*)d_out;

    const int smem = 2 * 13056 * (int)sizeof(u64);   // 208896 B
    cudaFuncSetAttribute(fused_kernel,
                         cudaFuncAttributeMaxDynamicSharedMemorySize, smem);

    fused_kernel<<<296, 512, smem>>>(pos, vel, rot, omg, mass, inertia,
                                     contacts, energy, fluid, Fext, tau,
                                     logA, logk, logb, conv_w, out);
}

// round 4
// speedup vs baseline: 1.0712x; 1.0712x over previous
#include <cuda_runtime.h>

typedef unsigned long long u64;

#define PHYS_DT (1.0f/60.0f)
#define NU_C    0.001f

__device__ __forceinline__ float softplusf(float x){
    return fmaxf(x, 0.0f) + log1pf(expf(-fabsf(x)));
}
__device__ __forceinline__ u64 pack2(float a, float b){
    u64 r; asm("mov.b64 %0, {%1,%2};" : "=l"(r) : "f"(a), "f"(b)); return r;
}
__device__ __forceinline__ float2 unpk(u64 a){
    float2 v; asm("mov.b64 {%0,%1}, %2;" : "=f"(v.x), "=f"(v.y) : "l"(a)); return v;
}
__device__ __forceinline__ u64 f2fma(u64 a, u64 b, u64 c){
    u64 d; asm("fma.rn.f32x2 %0,%1,%2,%3;" : "=l"(d) : "l"(a), "l"(b), "l"(c)); return d;
}
__device__ __forceinline__ u64 f2add(u64 a, u64 b){
    u64 d; asm("add.rn.f32x2 %0,%1,%2;" : "=l"(d) : "l"(a), "l"(b)); return d;
}
__device__ __forceinline__ u64 f2mul(u64 a, u64 b){
    u64 d; asm("mul.rn.f32x2 %0,%1,%2;" : "=l"(d) : "l"(a), "l"(b)); return d;
}

extern __shared__ __align__(16) u64 dynsmem64[];

// grid: 152 blocks x 512 threads, single wave.
// blocks [0,128): fluid — 2 sequential batch-pairs each, f32x2-packed conv,
//                 4-plane c-phase buffering, acc parked in shared.
// blocks [128,152): particles — 8 batches/block x 3 rounds.
__global__ void __launch_bounds__(512, 1) fused_kernel(
    const float* __restrict__ pos, const float* __restrict__ vel,
    const float* __restrict__ rot, const float* __restrict__ omg,
    const float* __restrict__ mass, const float* __restrict__ inertia,
    const float* __restrict__ contacts, const float* __restrict__ energy,
    const float* __restrict__ fluid, const float* __restrict__ Fext,
    const float* __restrict__ tau, const float* __restrict__ logA,
    const float* __restrict__ logk, const float* __restrict__ logb,
    const float* __restrict__ conv_w, float* __restrict__ out)
{
    if (blockIdx.x < 128) {
        // ===================== FLUID =====================
        __shared__ u64 Wp[81];       // packed weights
        __shared__ float Tsh[81];    // boundary-class weight sums
        __shared__ u64 redsh[48];    // per-warp psc partials (c x 16 warps)
        __shared__ u64 meansh[3];    // packed NEGATED mean per c

        u64* S    = dynsmem64;           // 4 planes x 4096 u64
        u64* PARK = dynsmem64 + 16384;   // 24 x 512 u64

        const int tid  = threadIdx.x;
        const int hs   = tid >> 8;        // h-half: 0 -> h 0..7, 1 -> 8..15
        const int d    = (tid >> 4) & 15;
        const int w    = tid & 15;
        const int h0   = hs << 3;
        const int warp = tid >> 5;
        const int lane = tid & 31;
        const bool dmv = (d > 0), dpv = (d < 15);

        if (tid < 81) {
            float x = conv_w[tid];
            Wp[tid] = pack2(x, x);
            int c = tid / 27, rem = tid % 27;
            int dc = rem / 9, hc = (rem % 9) / 3, wc = rem % 3;
            float ssum = 0.f;
            #pragma unroll
            for (int kd = 0; kd < 3; kd++) {
                if ((dc == 0 && kd == 0) || (dc == 2 && kd == 2)) continue;
                #pragma unroll
                for (int kh = 0; kh < 3; kh++) {
                    if ((hc == 0 && kh == 0) || (hc == 2 && kh == 2)) continue;
                    #pragma unroll
                    for (int kw = 0; kw < 3; kw++) {
                        if ((wc == 0 && kw == 0) || (wc == 2 && kw == 2)) continue;
                        ssum += conv_w[c*27 + kd*9 + kh*3 + kw];
                    }
                }
            }
            Tsh[tid] = ssum;
        }

        const int dcls = (d == 0) ? 0 : ((d == 15) ? 2 : 1);
        const int wcls = (w == 0) ? 0 : ((w == 15) ? 2 : 1);
        const u64 nu2 = pack2(NU_C, NU_C);
        const u64 dt62 = pack2(PHYS_DT/6.0f, PHYS_DT/6.0f);

        #pragma unroll 1
        for (int run = 0; run < 2; run++) {
            const int pair = blockIdx.x + run * 128;
            const int b0 = pair * 2;
            const float* f0 = fluid + (size_t)b0 * 12288;
            const float* f1 = f0 + 12288;

            __syncthreads();                       // planes free from prior run
            if (tid < 3) meansh[tid] = 0ull;

            // load u0 (both batches) into planes 0,1,2 by component
            for (int idx = tid; idx < 12288; idx += 512) {
                float a = f0[idx], bv = f1[idx];
                int cell = idx / 3, c = idx - cell*3;
                int dd = cell >> 8, hh2 = (cell >> 4) & 15, ww = cell & 15;
                S[c*4096 + dd*256 + hh2*16 + ww] = pack2(a, bv);
            }
            __syncthreads();

            int pl0 = 0, pl1 = 1, pl2 = 2, sp = 3;

            #pragma unroll 1
            for (int s = 0; s < 4; s++) {
                const float awf = (s == 0 || s == 3) ? 1.f : 2.f;
                const float cof = (s == 2) ? PHYS_DT : 0.5f*PHYS_DT;
                const u64 aw2 = pack2(awf, awf);
                const u64 co2 = pack2(cof, cof);
                const bool fin = (s == 3);

                #pragma unroll 1
                for (int c = 0; c < 3; c++) {
                    const int rd = (c == 0) ? pl0 : ((c == 1) ? pl1 : pl2);
                    const int wr = (c == 0) ? sp  : ((c == 1) ? pl0 : pl1);
                    const u64* bp  = S + rd*4096 + d*256 + w;
                    const u64* bpm = bp - 256;
                    const u64* bpp = bp + 256;
                    u64* wrp = S + wr*4096 + d*256 + w;

                    u64 W[27];
                    #pragma unroll
                    for (int t = 0; t < 27; t++) W[t] = Wp[c*27 + t];

                    float sA = Tsh[((c*3 + dcls)*3 + 0)*3 + wcls];
                    float sB = Tsh[((c*3 + dcls)*3 + 1)*3 + wcls];
                    float sC = Tsh[((c*3 + dcls)*3 + 2)*3 + wcls];
                    const u64 Sfirst = hs ? pack2(sB, sB) : pack2(sA, sA);
                    const u64 Smid   = pack2(sB, sB);
                    const u64 Slast  = hs ? pack2(sC, sC) : pack2(sB, sB);
                    const u64 negm   = meansh[c];

                    u64 acc[8];
                    if (s == 0) {
                        #pragma unroll
                        for (int hh = 0; hh < 8; hh++) acc[hh] = 0ull;
                    } else {
                        #pragma unroll
                        for (int hh = 0; hh < 8; hh++)
                            acc[hh] = PARK[(c*8 + hh)*512 + tid];
                    }

                    u64 u0p[8];
                    {
                        const int g0 = ((d << 8) + (h0 << 4) + w)*3 + c;
                        #pragma unroll
                        for (int hh = 0; hh < 8; hh++)
                            u0p[hh] = pack2(__ldg(f0 + g0 + hh*48),
                                            __ldg(f1 + g0 + hh*48));
                    }

                    const int hm = h0 - 1;
                    u64 r00 = (hs && dmv) ? bpm[hm*16] : 0ull;
                    u64 r10 =  hs         ? bp [hm*16] : 0ull;
                    u64 r20 = (hs && dpv) ? bpp[hm*16] : 0ull;
                    u64 r01 = dmv ? bpm[h0*16] : 0ull;
                    u64 r11 =       bp [h0*16];
                    u64 r21 = dpv ? bpp[h0*16] : 0ull;
                    u64 r02 = dmv ? bpm[(h0+1)*16] : 0ull;
                    u64 r12 =       bp [(h0+1)*16];
                    u64 r22 = dpv ? bpp[(h0+1)*16] : 0ull;
                    u64 psc = 0ull;

                    #pragma unroll
                    for (int hh = 0; hh < 8; hh++) {
                        const int h = h0 + hh;
                        u64 bb0 = f2mul(W[0], r00);
                        bb0 = f2fma(W[ 3], r01, bb0); bb0 = f2fma(W[ 6], r02, bb0);
                        bb0 = f2fma(W[ 9], r10, bb0); bb0 = f2fma(W[12], r11, bb0);
                        bb0 = f2fma(W[15], r12, bb0); bb0 = f2fma(W[18], r20, bb0);
                        bb0 = f2fma(W[21], r21, bb0); bb0 = f2fma(W[24], r22, bb0);
                        u64 bb1 = f2mul(W[1], r00);
                        bb1 = f2fma(W[ 4], r01, bb1); bb1 = f2fma(W[ 7], r02, bb1);
                        bb1 = f2fma(W[10], r10, bb1); bb1 = f2fma(W[13], r11, bb1);
                        bb1 = f2fma(W[16], r12, bb1); bb1 = f2fma(W[19], r20, bb1);
                        bb1 = f2fma(W[22], r21, bb1); bb1 = f2fma(W[25], r22, bb1);
                        u64 bb2 = f2mul(W[2], r00);
                        bb2 = f2fma(W[ 5], r01, bb2); bb2 = f2fma(W[ 8], r02, bb2);
                        bb2 = f2fma(W[11], r10, bb2); bb2 = f2fma(W[14], r11, bb2);
                        bb2 = f2fma(W[17], r12, bb2); bb2 = f2fma(W[20], r20, bb2);
                        bb2 = f2fma(W[23], r21, bb2); bb2 = f2fma(W[26], r22, bb2);

                        u64 lft = __shfl_up_sync(0xffffffffu, bb0, 1);
                        if (w == 0)  lft = 0ull;
                        u64 rgt = __shfl_down_sync(0xffffffffu, bb2, 1);
                        if (w == 15) rgt = 0ull;
                        u64 sum = f2add(f2add(lft, bb1), rgt);
                        const u64 Sc = (hh == 0) ? Sfirst : ((hh == 7) ? Slast : Smid);
                        sum = f2fma(negm, Sc, sum);     // de-mean correction
                        u64 kv = f2mul(nu2, sum);
                        acc[hh] = f2fma(aw2, kv, acc[hh]);
                        u64 val = fin ? f2fma(dt62, acc[hh], u0p[hh])
                                      : f2fma(co2,  kv,      u0p[hh]);
                        wrp[h*16] = val;
                        psc = f2add(psc, val);

                        r00 = r01; r01 = r02;
                        r10 = r11; r11 = r12;
                        r20 = r21; r21 = r22;
                        const int hn = h + 2;
                        const bool hv = (hn < 16);
                        const int hns = hv ? hn : 0;
                        r02 = (hv && dmv) ? bpm[hns*16] : 0ull;
                        r12 =  hv         ? bp [hns*16] : 0ull;
                        r22 = (hv && dpv) ? bpp[hns*16] : 0ull;
                    }

                    if (!fin) {
                        #pragma unroll
                        for (int hh = 0; hh < 8; hh++)
                            PARK[(c*8 + hh)*512 + tid] = acc[hh];
                    }
                    #pragma unroll
                    for (int off = 16; off; off >>= 1)
                        psc = f2add(psc, __shfl_xor_sync(0xffffffffu, psc, off));
                    if (lane == 0) redsh[c*16 + warp] = psc;
                    __syncthreads();
                }

                if (tid < 3) {
                    u64 sm = 0ull;
                    #pragma unroll
                    for (int q = 0; q < 16; q++) sm = f2add(sm, redsh[tid*16 + q]);
                    meansh[tid] = f2mul(sm, pack2(-1.0f/4096.0f, -1.0f/4096.0f));
                }
                { int t0 = pl2; pl2 = pl1; pl1 = pl0; pl0 = sp; sp = t0; }
                __syncthreads();
            }

            // final: demean raw (in planes pl0..pl2) and store both batches
            float* o0 = out + (size_t)b0 * 13313 + 1025;
            float* o1 = o0 + 13313;
            for (int idx = tid; idx < 12288; idx += 512) {
                int cell = idx / 3, c = idx - cell*3;
                int dd = cell >> 8, hh2 = (cell >> 4) & 15, ww = cell & 15;
                int pb_ = (c == 0) ? pl0 : ((c == 1) ? pl1 : pl2);
                u64 v = f2add(S[pb_*4096 + dd*256 + hh2*16 + ww], meansh[c]);
                float2 fv = unpk(v);
                o0[idx] = fv.x;
                o1[idx] = fv.y;
            }
        }
    } else {
        // ===================== PARTICLES =====================
        float* P = (float*)dynsmem64;
        const int sub = threadIdx.x >> 6;
        const int i   = threadIdx.x & 63;
        float*  ct   = P + sub*4680;                 // [64*65]
        float4* sp   = (float4*)(ct + 4160);         // [64]
        float4* sv   = sp + 64;                      // [64]
        float*  redw = ct + 4672;                    // [2]

        #pragma unroll 1
        for (int rnd = 0; rnd < 3; rnd++) {
            const int pb = ((int)blockIdx.x - 128)*8 + sub + rnd*192;
            const bool act = (pb < 512);
            const int b = act ? pb : 0;
            __syncthreads();   // shared reuse safe across rounds

            const int gi = b*64 + i;
            const float px=pos[gi*3+0], py=pos[gi*3+1], pz=pos[gi*3+2];
            const float vx=vel[gi*3+0], vy=vel[gi*3+1], vz=vel[gi*3+2];
            const float rw=rot[gi*4+0], rx=rot[gi*4+1], ry=rot[gi*4+2], rz=rot[gi*4+3];
            const float ox=omg[gi*3+0], oy=omg[gi*3+1], oz=omg[gi*3+2];
            const float Ix=inertia[gi*3+0], Iy=inertia[gi*3+1], Iz=inertia[gi*3+2];
            const float fx=Fext[gi*3+0], fy=Fext[gi*3+1], fz=Fext[gi*3+2];
            const float tx=tau[gi*3+0], ty=tau[gi*3+1], tz=tau[gi*3+2];
            const float m    = mass[gi];
            const float kk   = softplusf(logk[0]);
            const float bb   = softplusf(logb[0]);
            const float dragc= -0.5f*1.225f*0.47f*softplusf(logA[i]);
            const float minv = 1.0f/m;
            const float Iix=1.0f/fmaxf(Ix,1e-6f), Iiy=1.0f/fmaxf(Iy,1e-6f), Iiz=1.0f/fmaxf(Iz,1e-6f);

            #pragma unroll 8
            for (int r = 0; r < 64; r++)
                ct[i*65 + r] = contacts[b*4096 + r*64 + i];
            sp[i] = make_float4(px,py,pz,0.f);
            sv[i] = make_float4(vx,vy,vz,0.f);
            __syncthreads();

            float cpx=px,cpy=py,cpz=pz, cvx=vx,cvy=vy,cvz=vz;
            float qw=rw,qx=rx,qy=ry,qz=rz, cox=ox,coy=oy,coz=oz;
            float aPx=0,aPy=0,aPz=0, aVx=0,aVy=0,aVz=0;
            float aRw=0,aRx=0,aRy=0,aRz=0, aWx=0,aWy=0,aWz=0, aE=0;
            float dvx,dvy,dvz, drw,drx,dry,drz, dwx,dwy,dwz, dE;

            auto deriv = [&]() {
                float vm = fmaxf(sqrtf(cvx*cvx + cvy*cvy + cvz*cvz), 1e-6f);
                float dc = dragc * vm;
                float fdx = dc*cvx, fdy = dc*cvy, fdz = dc*cvz;
                float fcx = 0.f, fcy = 0.f, fcz = 0.f;
                #pragma unroll 8
                for (int j = 0; j < 64; j++) {
                    float4 pj = sp[j];
                    float4 vj = sv[j];
                    float dx = pj.x - cpx, dy = pj.y - cpy, dz = pj.z - cpz;
                    float d2 = fmaf(dx,dx, fmaf(dy,dy, dz*dz));
                    float ri = rsqrtf(fmaxf(d2, 1e-12f));
                    float pen = fmaxf(1.0f - d2*ri, 0.0f);
                    float kp = kk * pen * ri;
                    float cf = bb * ct[j*65 + i];
                    fcx += kp*dx + cf*(vj.x - cvx);
                    fcy += kp*dy + cf*(vj.y - cvy);
                    fcz += kp*dz + cf*(vj.z - cvz);
                }
                dvx = (fx + fdx + fcx) * minv;
                dvy = (fy + fdy + fcy) * minv;
                dvz = (fz + fdz + fcz) * minv - 9.81f;
                float Iox = Ix*cox, Ioy = Iy*coy, Ioz = Iz*coz;
                dwx = (tx - (coy*Ioz - coz*Ioy)) * Iix;
                dwy = (ty - (coz*Iox - cox*Ioz)) * Iiy;
                dwz = (tz - (cox*Ioy - coy*Iox)) * Iiz;
                drw = 0.5f*(-qx*cox - qy*coy - qz*coz);
                drx = 0.5f*( qw*cox + qy*coz - qz*coy);
                dry = 0.5f*( qw*coy - qx*coz + qz*cox);
                drz = 0.5f*( qw*coz + qx*coy - qy*cox);
                dE  = (fx + fdx)*cvx + (fy + fdy)*cvy + (fz + fdz)*cvz;
            };
            auto accum = [&](float wgt) {
                aPx += wgt*cvx; aPy += wgt*cvy; aPz += wgt*cvz;
                aVx += wgt*dvx; aVy += wgt*dvy; aVz += wgt*dvz;
                aRw += wgt*drw; aRx += wgt*drx; aRy += wgt*dry; aRz += wgt*drz;
                aWx += wgt*dwx; aWy += wgt*dwy; aWz += wgt*dwz;
                aE  += wgt*dE;
            };
            auto advance = [&](float h) {
                float npx = px + h*cvx, npy = py + h*cvy, npz = pz + h*cvz;
                cvx = vx + h*dvx; cvy = vy + h*dvy; cvz = vz + h*dvz;
                cpx = npx; cpy = npy; cpz = npz;
                float nqw = rw + h*drw, nqx = rx + h*drx, nqy = ry + h*dry, nqz = rz + h*drz;
                float nn  = fmaxf(sqrtf(nqw*nqw + nqx*nqx + nqy*nqy + nqz*nqz), 1e-12f);
                float inn = 1.0f/nn;
                qw = nqw*inn; qx = nqx*inn; qy = nqy*inn; qz = nqz*inn;
                cox = ox + h*dwx; coy = oy + h*dwy; coz = oz + h*dwz;
                __syncthreads();
                sp[i] = make_float4(cpx,cpy,cpz,0.f);
                sv[i] = make_float4(cvx,cvy,cvz,0.f);
                __syncthreads();
            };

            const int base = b * 13313;

            deriv(); accum(1.f);
            if (act) {
                int fb = base + 832 + i*3;
                out[fb+0] = fx + m*dvx;
                out[fb+1] = fy + m*dvy;
                out[fb+2] = fz + m*dvz;
            }
            advance(0.5f*PHYS_DT);
            deriv(); accum(2.f);
            advance(0.5f*PHYS_DT);
            deriv(); accum(2.f);
            advance(PHYS_DT);
            deriv(); accum(1.f);

            const float s6 = PHYS_DT/6.0f;
            if (act) {
                out[base + i*3+0] = px + s6*aPx;
                out[base + i*3+1] = py + s6*aPy;
                out[base + i*3+2] = pz + s6*aPz;
                out[base + 192 + i*3+0] = vx + s6*aVx;
                out[base + 192 + i*3+1] = vy + s6*aVy;
                out[base + 192 + i*3+2] = vz + s6*aVz;
                float nqw = rw + s6*aRw, nqx = rx + s6*aRx, nqy = ry + s6*aRy, nqz = rz + s6*aRz;
                float nn  = fmaxf(sqrtf(nqw*nqw + nqx*nqx + nqy*nqy + nqz*nqz), 1e-12f);
                float inn = 1.0f/nn;
                out[base + 384 + i*4+0] = nqw*inn;
                out[base + 384 + i*4+1] = nqx*inn;
                out[base + 384 + i*4+2] = nqy*inn;
                out[base + 384 + i*4+3] = nqz*inn;
                out[base + 640 + i*3+0] = ox + s6*aWx;
                out[base + 640 + i*3+1] = oy + s6*aWy;
                out[base + 640 + i*3+2] = oz + s6*aWz;
            }
            float e = aE;
            #pragma unroll
            for (int off = 16; off; off >>= 1)
                e += __shfl_down_sync(0xffffffffu, e, off);
            if ((i & 31) == 0) redw[i >> 5] = e;
            __syncthreads();
            if (act && i == 0) out[base + 1024] = energy[b] + s6*(redw[0] + redw[1]);
        }
    }
}

// ---------------------------------------------------------------------------
extern "C" void kernel_launch(void* const* d_in, const int* in_sizes, int n_in,
                              void* d_out, int out_size)
{
    (void)in_sizes; (void)n_in; (void)out_size;
    const float* pos      = (const float*)d_in[0];
    const float* vel      = (const float*)d_in[1];
    const float* rot      = (const float*)d_in[2];
    const float* omg      = (const float*)d_in[3];
    const float* mass     = (const float*)d_in[4];
    const float* inertia  = (const float*)d_in[5];
    const float* contacts = (const float*)d_in[6];
    const float* energy   = (const float*)d_in[7];
    const float* fluid    = (const float*)d_in[8];
    const float* Fext     = (const float*)d_in[9];
    const float* tau      = (const float*)d_in[10];
    const float* logA     = (const float*)d_in[11];
    const float* logk     = (const float*)d_in[12];
    const float* logb     = (const float*)d_in[13];
    const float* conv_w   = (const float*)d_in[14];
    float* out = (float*)d_out;

    // 4 planes x 4096 u64 + 24 x 512 u64 park = 229376 B dynamic shared
    const int smem = (16384 + 12288) * (int)sizeof(u64);
    cudaFuncSetAttribute(fused_kernel,
                         cudaFuncAttributeMaxDynamicSharedMemorySize, smem);

    fused_kernel<<<152, 512, smem>>>(pos, vel, rot, omg, mass, inertia,
                                     contacts, energy, fluid, Fext, tau,
                                     logA, logk, logb, conv_w, out);
}

// round 5
// speedup vs baseline: 1.3406x; 1.2514x over previous
#include <cuda_runtime.h>

typedef unsigned long long u64;

#define PHYS_DT (1.0f/60.0f)
#define NU_C    0.001f

__device__ __forceinline__ float softplusf(float x){
    return fmaxf(x, 0.0f) + log1pf(expf(-fabsf(x)));
}
__device__ __forceinline__ u64 pack2(float a, float b){
    u64 r; asm("mov.b64 %0, {%1,%2};" : "=l"(r) : "f"(a), "f"(b)); return r;
}
__device__ __forceinline__ float2 unpk(u64 a){
    float2 v; asm("mov.b64 {%0,%1}, %2;" : "=f"(v.x), "=f"(v.y) : "l"(a)); return v;
}
__device__ __forceinline__ u64 f2fma(u64 a, u64 b, u64 c){
    u64 d; asm("fma.rn.f32x2 %0,%1,%2,%3;" : "=l"(d) : "l"(a), "l"(b), "l"(c)); return d;
}
__device__ __forceinline__ u64 f2add(u64 a, u64 b){
    u64 d; asm("add.rn.f32x2 %0,%1,%2;" : "=l"(d) : "l"(a), "l"(b)); return d;
}
__device__ __forceinline__ u64 f2mul(u64 a, u64 b){
    u64 d; asm("mul.rn.f32x2 %0,%1,%2;" : "=l"(d) : "l"(a), "l"(b)); return d;
}

extern __shared__ __align__(16) u64 dynsmem64[];

// One RK stage, one component, one (d,w,h-half) thread.
// S=0: state=u0 (from r11), FACC = -(1/3) r11.          writes y1, parks FACC.
// S=1: FACC += (1/3) r11, y2 = u0 + dt/2 k2 (u0 prefetch). parks FACC.
// S=2: FACC += (2/3) r11, y3 = u0 + dt  k3 (u0 prefetch). parks FACC.
// S=3: FACC += (1/3) r11 + dt/6 k4; writes FACC to plane; psc over FACC.
// Weights are pre-scaled by NU; Scn* = (-mean_prev) * (NU * boundary weight-sum).
template<int S>
__device__ __forceinline__ u64 fluid_phase(
    const u64* __restrict__ bp, u64* __restrict__ wrp,
    const u64* __restrict__ Wc, u64* __restrict__ parkc,
    const float* __restrict__ g0a, const float* __restrict__ g0b,
    u64 ScnF, u64 ScnM, u64 ScnL,
    bool dmv, bool dpv, int w, int h0, int hs)
{
    const u64* bpm = bp - 256;
    const u64* bpp = bp + 256;

    u64 u0q[4];
    if (S == 1 || S == 2) {
        #pragma unroll
        for (int t = 0; t < 4; t++)
            u0q[t] = pack2(__ldg(g0a + t*48), __ldg(g0b + t*48));
    }

    u64 W[27];
    #pragma unroll
    for (int t = 0; t < 27; t++) W[t] = Wc[t];

    const u64 co2 = (S == 2) ? pack2(PHYS_DT, PHYS_DT)
                             : pack2(0.5f*PHYS_DT, 0.5f*PHYS_DT);
    const u64 fw  = (S == 0) ? pack2(-1.0f/3.0f, -1.0f/3.0f)
                  : (S == 2) ? pack2( 2.0f/3.0f,  2.0f/3.0f)
                             : pack2( 1.0f/3.0f,  1.0f/3.0f);
    const u64 dt6 = pack2(PHYS_DT/6.0f, PHYS_DT/6.0f);

    const int hm = hs ? (h0 - 1) : 0;
    u64 r00 = (hs && dmv) ? bpm[hm*16] : 0ull;
    u64 r10 =  hs         ? bp [hm*16] : 0ull;
    u64 r20 = (hs && dpv) ? bpp[hm*16] : 0ull;
    u64 r01 = dmv ? bpm[h0*16] : 0ull;
    u64 r11 =       bp [h0*16];
    u64 r21 = dpv ? bpp[h0*16] : 0ull;
    u64 r02 = dmv ? bpm[(h0+1)*16] : 0ull;
    u64 r12 =       bp [(h0+1)*16];
    u64 r22 = dpv ? bpp[(h0+1)*16] : 0ull;
    u64 psc = 0ull;

    #pragma unroll
    for (int hh = 0; hh < 8; hh++) {
        const int h = h0 + hh;
        u64 fa = (S > 0) ? parkc[hh*512] : 0ull;

        u64 bb0 = f2mul(W[0], r00);
        bb0 = f2fma(W[ 3], r01, bb0); bb0 = f2fma(W[ 6], r02, bb0);
        bb0 = f2fma(W[ 9], r10, bb0); bb0 = f2fma(W[12], r11, bb0);
        bb0 = f2fma(W[15], r12, bb0); bb0 = f2fma(W[18], r20, bb0);
        bb0 = f2fma(W[21], r21, bb0); bb0 = f2fma(W[24], r22, bb0);
        u64 bb1 = f2mul(W[1], r00);
        bb1 = f2fma(W[ 4], r01, bb1); bb1 = f2fma(W[ 7], r02, bb1);
        bb1 = f2fma(W[10], r10, bb1); bb1 = f2fma(W[13], r11, bb1);
        bb1 = f2fma(W[16], r12, bb1); bb1 = f2fma(W[19], r20, bb1);
        bb1 = f2fma(W[22], r21, bb1); bb1 = f2fma(W[25], r22, bb1);
        u64 bb2 = f2mul(W[2], r00);
        bb2 = f2fma(W[ 5], r01, bb2); bb2 = f2fma(W[ 8], r02, bb2);
        bb2 = f2fma(W[11], r10, bb2); bb2 = f2fma(W[14], r11, bb2);
        bb2 = f2fma(W[17], r12, bb2); bb2 = f2fma(W[20], r20, bb2);
        bb2 = f2fma(W[23], r21, bb2); bb2 = f2fma(W[26], r22, bb2);

        u64 lft = __shfl_up_sync(0xffffffffu, bb0, 1);
        if (w == 0)  lft = 0ull;
        u64 rgt = __shfl_down_sync(0xffffffffu, bb2, 1);
        if (w == 15) rgt = 0ull;
        u64 sum = f2add(f2add(lft, bb1), rgt);    // NU * conv(stored)
        if (S > 0)
            sum = f2add(sum, (hh == 0) ? ScnF : ((hh == 7) ? ScnL : ScnM));

        u64 val;
        if (S == 0) {
            fa  = f2mul(fw, r11);                  // FACC = -u0/3
            val = f2fma(co2, sum, r11);            // y1 = u0 + dt/2 k1
        } else if (S == 3) {
            fa  = f2fma(fw, r11, fa);              // += y3/3
            fa  = f2fma(dt6, sum, fa);             // += dt/6 k4
            val = fa;                              // FACC -> plane
        } else {
            fa  = f2fma(fw, r11, fa);
            val = f2fma(co2, sum, u0q[hh & 3]);
            if (hh < 4)
                u0q[hh] = pack2(__ldg(g0a + (hh+4)*48), __ldg(g0b + (hh+4)*48));
        }
        if (S < 3) parkc[hh*512] = fa;
        wrp[h*16] = val;
        psc = f2add(psc, val);

        r00 = r01; r01 = r02;
        r10 = r11; r11 = r12;
        r20 = r21; r21 = r22;
        const int hn = h + 2;
        const bool hv = (hn < 16);
        const int hns = hv ? hn : 0;
        r02 = (hv && dmv) ? bpm[hns*16] : 0ull;
        r12 =  hv         ? bp [hns*16] : 0ull;
        r22 = (hv && dpv) ? bpp[hns*16] : 0ull;
    }
    return psc;
}

#define RUN_STAGE(S_) do {                                                    \
    _Pragma("unroll 1")                                                       \
    for (int c = 0; c < 3; c++) {                                             \
        const int rdp = (c + 4 - (S_)) & 3;                                   \
        const int wpl = (c + 3 - (S_)) & 3;                                   \
        u64 ScnF = 0ull, ScnM = 0ull, ScnL = 0ull;                            \
        if ((S_) > 0) {                                                       \
            float sA = Tsh[((c*3 + dcls)*3 + 0)*3 + wcls];                    \
            float sB = Tsh[((c*3 + dcls)*3 + 1)*3 + wcls];                    \
            float sC = Tsh[((c*3 + dcls)*3 + 2)*3 + wcls];                    \
            u64 negm = meansh[c];                                             \
            ScnF = f2mul(negm, hs ? pack2(sB,sB) : pack2(sA,sA));             \
            ScnM = f2mul(negm, pack2(sB,sB));                                 \
            ScnL = f2mul(negm, hs ? pack2(sC,sC) : pack2(sB,sB));             \
        }                                                                     \
        const int g0 = ((d<<8)+(h0<<4)+w)*3 + c;                              \
        u64 psc = fluid_phase<S_>(Sm + rdp*4096 + d*256 + w,                  \
                                  Sm + wpl*4096 + d*256 + w,                  \
                                  Wp + c*27, PARK + c*4096 + tid,             \
                                  f0 + g0, f1 + g0,                           \
                                  ScnF, ScnM, ScnL, dmv, dpv, w, h0, hs);     \
        _Pragma("unroll")                                                     \
        for (int off = 16; off; off >>= 1)                                    \
            psc = f2add(psc, __shfl_xor_sync(0xffffffffu, psc, off));         \
        if (lane == 0) redsh[c*16 + warp] = psc;                              \
        __syncthreads();                                                      \
    }                                                                         \
    if (tid < 3) {                                                            \
        u64 sm_ = 0ull;                                                       \
        _Pragma("unroll")                                                     \
        for (int q = 0; q < 16; q++) sm_ = f2add(sm_, redsh[tid*16 + q]);     \
        meansh[tid] = f2mul(sm_, pack2(-1.0f/4096.0f, -1.0f/4096.0f));        \
    }                                                                         \
    __syncthreads();                                                          \
} while (0)

// grid: 152 blocks x 512 threads, single wave.
// blocks [0,128): fluid — 2 sequential batch-pairs, f32x2-packed conv.
// blocks [128,152): particles — 8 batches/block x 3 rounds.
__global__ void __launch_bounds__(512, 1) fused_kernel(
    const float* __restrict__ pos, const float* __restrict__ vel,
    const float* __restrict__ rot, const float* __restrict__ omg,
    const float* __restrict__ mass, const float* __restrict__ inertia,
    const float* __restrict__ contacts, const float* __restrict__ energy,
    const float* __restrict__ fluid, const float* __restrict__ Fext,
    const float* __restrict__ tau, const float* __restrict__ logA,
    const float* __restrict__ logk, const float* __restrict__ logb,
    const float* __restrict__ conv_w, float* __restrict__ out)
{
    if (blockIdx.x < 128) {
        // ===================== FLUID =====================
        __shared__ u64 Wp[81];       // packed weights * NU
        __shared__ float Tsh[81];    // NU * boundary-class weight sums
        __shared__ u64 redsh[48];
        __shared__ u64 meansh[3];    // packed NEGATED mean per c

        u64* Sm   = dynsmem64;           // 4 planes x 4096 u64
        u64* PARK = dynsmem64 + 16384;   // 3 x 8 x 512 u64 (FACC park)

        const int tid  = threadIdx.x;
        const int hs   = tid >> 8;
        const int d    = (tid >> 4) & 15;
        const int w    = tid & 15;
        const int h0   = hs << 3;
        const int warp = tid >> 5;
        const int lane = tid & 31;
        const bool dmv = (d > 0), dpv = (d < 15);

        if (tid < 81) {
            float x = conv_w[tid];
            Wp[tid] = pack2(NU_C*x, NU_C*x);
            int c = tid / 27, rem = tid % 27;
            int dc = rem / 9, hc = (rem % 9) / 3, wc = rem % 3;
            float ssum = 0.f;
            #pragma unroll
            for (int kd = 0; kd < 3; kd++) {
                if ((dc == 0 && kd == 0) || (dc == 2 && kd == 2)) continue;
                #pragma unroll
                for (int kh = 0; kh < 3; kh++) {
                    if ((hc == 0 && kh == 0) || (hc == 2 && kh == 2)) continue;
                    #pragma unroll
                    for (int kw = 0; kw < 3; kw++) {
                        if ((wc == 0 && kw == 0) || (wc == 2 && kw == 2)) continue;
                        ssum += conv_w[c*27 + kd*9 + kh*3 + kw];
                    }
                }
            }
            Tsh[tid] = NU_C * ssum;
        }

        const int dcls = (d == 0) ? 0 : ((d == 15) ? 2 : 1);
        const int wcls = (w == 0) ? 0 : ((w == 15) ? 2 : 1);

        #pragma unroll 1
        for (int run = 0; run < 2; run++) {
            const int b0 = (blockIdx.x + run * 128) * 2;
            const float* f0 = fluid + (size_t)b0 * 12288;
            const float* f1 = f0 + 12288;

            __syncthreads();               // planes free from prior run
            // load u0 (both batches) into planes 0,1,2
            for (int idx = tid; idx < 12288; idx += 512) {
                float a = f0[idx], bv = f1[idx];
                int cell = idx / 3, c = idx - cell*3;
                int dd = cell >> 8, hh2 = (cell >> 4) & 15, ww = cell & 15;
                Sm[c*4096 + dd*256 + hh2*16 + ww] = pack2(a, bv);
            }
            __syncthreads();

            RUN_STAGE(0);
            RUN_STAGE(1);
            RUN_STAGE(2);
            RUN_STAGE(3);

            // FACC landed in plane c for component c; demean and store.
            float* o0 = out + (size_t)b0 * 13313 + 1025;
            float* o1 = o0 + 13313;
            for (int idx = tid; idx < 12288; idx += 512) {
                int cell = idx / 3, c = idx - cell*3;
                int dd = cell >> 8, hh2 = (cell >> 4) & 15, ww = cell & 15;
                u64 v = f2add(Sm[c*4096 + dd*256 + hh2*16 + ww], meansh[c]);
                float2 fv = unpk(v);
                o0[idx] = fv.x;
                o1[idx] = fv.y;
            }
        }
    } else {
        // ===================== PARTICLES =====================
        float* P = (float*)dynsmem64;
        const int sub = threadIdx.x >> 6;
        const int i   = threadIdx.x & 63;
        float*  ct   = P + sub*4680;
        float4* sp   = (float4*)(ct + 4160);
        float4* sv   = sp + 64;
        float*  redw = ct + 4672;

        #pragma unroll 1
        for (int rnd = 0; rnd < 3; rnd++) {
            const int pb = ((int)blockIdx.x - 128)*8 + sub + rnd*192;
            const bool act = (pb < 512);
            const int b = act ? pb : 0;
            __syncthreads();

            const int gi = b*64 + i;
            const float px=pos[gi*3+0], py=pos[gi*3+1], pz=pos[gi*3+2];
            const float vx=vel[gi*3+0], vy=vel[gi*3+1], vz=vel[gi*3+2];
            const float rw=rot[gi*4+0], rx=rot[gi*4+1], ry=rot[gi*4+2], rz=rot[gi*4+3];
            const float ox=omg[gi*3+0], oy=omg[gi*3+1], oz=omg[gi*3+2];
            const float Ix=inertia[gi*3+0], Iy=inertia[gi*3+1], Iz=inertia[gi*3+2];
            const float fx=Fext[gi*3+0], fy=Fext[gi*3+1], fz=Fext[gi*3+2];
            const float tx=tau[gi*3+0], ty=tau[gi*3+1], tz=tau[gi*3+2];
            const float m    = mass[gi];
            const float kk   = softplusf(logk[0]);
            const float bb   = softplusf(logb[0]);
            const float dragc= -0.5f*1.225f*0.47f*softplusf(logA[i]);
            const float minv = 1.0f/m;
            const float Iix=1.0f/fmaxf(Ix,1e-6f), Iiy=1.0f/fmaxf(Iy,1e-6f), Iiz=1.0f/fmaxf(Iz,1e-6f);

            #pragma unroll 8
            for (int r = 0; r < 64; r++)
                ct[i*65 + r] = contacts[b*4096 + r*64 + i];
            sp[i] = make_float4(px,py,pz,0.f);
            sv[i] = make_float4(vx,vy,vz,0.f);
            __syncthreads();

            float cpx=px,cpy=py,cpz=pz, cvx=vx,cvy=vy,cvz=vz;
            float qw=rw,qx=rx,qy=ry,qz=rz, cox=ox,coy=oy,coz=oz;
            float aPx=0,aPy=0,aPz=0, aVx=0,aVy=0,aVz=0;
            float aRw=0,aRx=0,aRy=0,aRz=0, aWx=0,aWy=0,aWz=0, aE=0;
            float dvx,dvy,dvz, drw,drx,dry,drz, dwx,dwy,dwz, dE;

            auto deriv = [&]() {
                float vm = fmaxf(sqrtf(cvx*cvx + cvy*cvy + cvz*cvz), 1e-6f);
                float dc = dragc * vm;
                float fdx = dc*cvx, fdy = dc*cvy, fdz = dc*cvz;
                float fcx = 0.f, fcy = 0.f, fcz = 0.f;
                #pragma unroll 8
                for (int j = 0; j < 64; j++) {
                    float4 pj = sp[j];
                    float4 vj = sv[j];
                    float dx = pj.x - cpx, dy = pj.y - cpy, dz = pj.z - cpz;
                    float d2 = fmaf(dx,dx, fmaf(dy,dy, dz*dz));
                    float ri = rsqrtf(fmaxf(d2, 1e-12f));
                    float pen = fmaxf(1.0f - d2*ri, 0.0f);
                    float kp = kk * pen * ri;
                    float cf = bb * ct[j*65 + i];
                    fcx += kp*dx + cf*(vj.x - cvx);
                    fcy += kp*dy + cf*(vj.y - cvy);
                    fcz += kp*dz + cf*(vj.z - cvz);
                }
                dvx = (fx + fdx + fcx) * minv;
                dvy = (fy + fdy + fcy) * minv;
                dvz = (fz + fdz + fcz) * minv - 9.81f;
                float Iox = Ix*cox, Ioy = Iy*coy, Ioz = Iz*coz;
                dwx = (tx - (coy*Ioz - coz*Ioy)) * Iix;
                dwy = (ty - (coz*Iox - cox*Ioz)) * Iiy;
                dwz = (tz - (cox*Ioy - coy*Iox)) * Iiz;
                drw = 0.5f*(-qx*cox - qy*coy - qz*coz);
                drx = 0.5f*( qw*cox + qy*coz - qz*coy);
                dry = 0.5f*( qw*coy - qx*coz + qz*cox);
                drz = 0.5f*( qw*coz + qx*coy - qy*cox);
                dE  = (fx + fdx)*cvx + (fy + fdy)*cvy + (fz + fdz)*cvz;
            };
            auto accum = [&](float wgt) {
                aPx += wgt*cvx; aPy += wgt*cvy; aPz += wgt*cvz;
                aVx += wgt*dvx; aVy += wgt*dvy; aVz += wgt*dvz;
                aRw += wgt*drw; aRx += wgt*drx; aRy += wgt*dry; aRz += wgt*drz;
                aWx += wgt*dwx; aWy += wgt*dwy; aWz += wgt*dwz;
                aE  += wgt*dE;
            };
            auto advance = [&](float h) {
                float npx = px + h*cvx, npy = py + h*cvy, npz = pz + h*cvz;
                cvx = vx + h*dvx; cvy = vy + h*dvy; cvz = vz + h*dvz;
                cpx = npx; cpy = npy; cpz = npz;
                float nqw = rw + h*drw, nqx = rx + h*drx, nqy = ry + h*dry, nqz = rz + h*drz;
                float nn  = fmaxf(sqrtf(nqw*nqw + nqx*nqx + nqy*nqy + nqz*nqz), 1e-12f);
                float inn = 1.0f/nn;
                qw = nqw*inn; qx = nqx*inn; qy = nqy*inn; qz = nqz*inn;
                cox = ox + h*dwx; coy = oy + h*dwy; coz = oz + h*dwz;
                __syncthreads();
                sp[i] = make_float4(cpx,cpy,cpz,0.f);
                sv[i] = make_float4(cvx,cvy,cvz,0.f);
                __syncthreads();
            };

            const int base = b * 13313;

            deriv(); accum(1.f);
            if (act) {
                int fb = base + 832 + i*3;
                out[fb+0] = fx + m*dvx;
                out[fb+1] = fy + m*dvy;
                out[fb+2] = fz + m*dvz;
            }
            advance(0.5f*PHYS_DT);
            deriv(); accum(2.f);
            advance(0.5f*PHYS_DT);
            deriv(); accum(2.f);
            advance(PHYS_DT);
            deriv(); accum(1.f);

            const float s6 = PHYS_DT/6.0f;
            if (act) {
                out[base + i*3+0] = px + s6*aPx;
                out[base + i*3+1] = py + s6*aPy;
                out[base + i*3+2] = pz + s6*aPz;
                out[base + 192 + i*3+0] = vx + s6*aVx;
                out[base + 192 + i*3+1] = vy + s6*aVy;
                out[base + 192 + i*3+2] = vz + s6*aVz;
                float nqw = rw + s6*aRw, nqx = rx + s6*aRx, nqy = ry + s6*aRy, nqz = rz + s6*aRz;
                float nn  = fmaxf(sqrtf(nqw*nqw + nqx*nqx + nqy*nqy + nqz*nqz), 1e-12f);
                float inn = 1.0f/nn;
                out[base + 384 + i*4+0] = nqw*inn;
                out[base + 384 + i*4+1] = nqx*inn;
                out[base + 384 + i*4+2] = nqy*inn;
                out[base + 384 + i*4+3] = nqz*inn;
                out[base + 640 + i*3+0] = ox + s6*aWx;
                out[base + 640 + i*3+1] = oy + s6*aWy;
                out[base + 640 + i*3+2] = oz + s6*aWz;
            }
            float e = aE;
            #pragma unroll
            for (int off = 16; off; off >>= 1)
                e += __shfl_down_sync(0xffffffffu, e, off);
            if ((i & 31) == 0) redw[i >> 5] = e;
            __syncthreads();
            if (act && i == 0) out[base + 1024] = energy[b] + s6*(redw[0] + redw[1]);
        }
    }
}

// ---------------------------------------------------------------------------
extern "C" void kernel_launch(void* const* d_in, const int* in_sizes, int n_in,
                              void* d_out, int out_size)
{
    (void)in_sizes; (void)n_in; (void)out_size;
    const float* pos      = (const float*)d_in[0];
    const float* vel      = (const float*)d_in[1];
    const float* rot      = (const float*)d_in[2];
    const float* omg      = (const float*)d_in[3];
    const float* mass     = (const float*)d_in[4];
    const float* inertia  = (const float*)d_in[5];
    const float* contacts = (const float*)d_in[6];
    const float* energy   = (const float*)d_in[7];
    const float* fluid    = (const float*)d_in[8];
    const float* Fext     = (const float*)d_in[9];
    const float* tau      = (const float*)d_in[10];
    const float* logA     = (const float*)d_in[11];
    const float* logk     = (const float*)d_in[12];
    const float* logb     = (const float*)d_in[13];
    const float* conv_w   = (const float*)d_in[14];
    float* out = (float*)d_out;

    // 4 planes x 4096 u64 + 3*8*512 u64 FACC park = 229376 B dynamic shared
    const int smem = (16384 + 12288) * (int)sizeof(u64);
    cudaFuncSetAttribute(fused_kernel,
                         cudaFuncAttributeMaxDynamicSharedMemorySize, smem);

    fused_kernel<<<152, 512, smem>>>(pos, vel, rot, omg, mass, inertia,
                                     contacts, energy, fluid, Fext, tau,
                                     logA, logk, logb, conv_w, out);
}